// round 3
// baseline (speedup 1.0000x reference)
#include <cuda_runtime.h>
#include <cuda_bf16.h>

// MedianFilter1D: k=9 sliding median along last axis, replicate padding.
// x: [B, C, L] fp32, L = 8192, B*C = 2048 rows.
//
// R3 changes vs R2 (26.9us wall / 21.5us kernel, alu=58.6% occ=53.4% issue=43.9%):
//  - Row split into 4 CTA segments (grid 8192, 8.2KB smem, ITERS=2):
//    kills the 2.77-wave quantization tail and lowers unroll/reg pressure.
//  - __launch_bounds__(256,6): regs<=42, theoretical occupancy 75%.
//  - Same 17-op/output median math (sorted-triple identity + hoisted
//    reductions + shared sorted pairs).

#define ROW_L   8192
#define SEG     2048
#define SEGS_PER_ROW (ROW_L / SEG)     // 4
#define PAD     4
#define NTHREADS 256
#define ITERS   (SEG / 4 / NTHREADS)   // 2

__device__ __forceinline__ void cswap(float& a, float& b) {
    float lo = fminf(a, b);
    b = fmaxf(a, b);
    a = lo;
}

__device__ __forceinline__ void sort3(float& a, float& b, float& c) {
    cswap(a, b);
    cswap(b, c);
    cswap(a, b);
}

__device__ __forceinline__ float med3(float a, float b, float c) {
    return fmaxf(fminf(a, b), fminf(fmaxf(a, b), c));   // 4 ops
}

// Insert x into sorted pair (p0 <= p1) -> sorted triple (4 ops)
__device__ __forceinline__ void insert3(float x, float p0, float p1,
                                        float& a0, float& a1, float& a2) {
    a0 = fminf(x, p0);
    float m = fmaxf(x, p0);
    a1 = fminf(m, p1);
    a2 = fmaxf(m, p1);
}

__global__ __launch_bounds__(NTHREADS, 6)
void median9_kernel(const float* __restrict__ x, float* __restrict__ y) {
    __shared__ __align__(16) float s[SEG + 2 * PAD];

    const int row = blockIdx.x / SEGS_PER_ROW;
    const int seg = blockIdx.x % SEGS_PER_ROW;
    const int segbase = seg * SEG;                  // segment start within row
    const float* xr = x + (size_t)row * ROW_L;
    float* yo       = y + (size_t)row * ROW_L + segbase;
    const int t = threadIdx.x;

    // ---- Stage segment into smem (float4, coalesced). s[PAD+i]=xr[segbase+i].
    const float4* x4 = (const float4*)(xr + segbase);
    #pragma unroll
    for (int j = 0; j < ITERS; j++) {
        int i = t + NTHREADS * j;
        *(float4*)&s[PAD + 4 * i] = x4[i];
    }
    // ---- Halos: clamped global loads (replicate at true row edges, real
    //      neighbor data at interior segment boundaries). 8 scalar LDGs/CTA.
    if (t < 2 * PAD) {
        int pos = (t < PAD) ? (segbase - PAD + t)            // left halo
                            : (segbase + SEG + (t - PAD));   // right halo
        pos = min(max(pos, 0), ROW_L - 1);
        int sidx = (t < PAD) ? t : (PAD + SEG + (t - PAD));
        s[sidx] = xr[pos];
    }
    __syncthreads();

    // ---- 4 consecutive outputs per iteration from 12 values. ----
    // Output i (segment-local) uses window s[i .. i+8].
    #pragma unroll
    for (int j = 0; j < ITERS; j++) {
        const int o = 4 * t + 4 * NTHREADS * j;

        float4 va = *(const float4*)&s[o];         // v0..v3
        float4 vb = *(const float4*)&s[o + 4];     // v4..v7
        float4 vc = *(const float4*)&s[o + 8];     // v8..v11

        // Shared middle triples T1={v3,v4,v5}, T2={v6,v7,v8}, sorted.
        float b0 = va.w, b1 = vb.x, b2 = vb.y; sort3(b0, b1, b2);
        float c0 = vb.z, c1 = vb.w, c2 = vc.x; sort3(c0, c1, c2);

        // Hoisted reductions over the shared triples.
        const float mm = fmaxf(b0, c0);
        const float nn = fminf(b2, c2);
        const float p  = fminf(b1, c1);
        const float q  = fmaxf(b1, c1);

        // Sorted pairs reused by the a-triples.
        float s1 = fminf(va.y, va.z), s2 = fmaxf(va.y, va.z);  // (v1,v2)
        float t1 = fminf(vc.y, vc.z), t2 = fmaxf(vc.y, vc.z);  // (v9,v10)

        float4 r;
        float a0, a1, a2;

        // out o:   {v0,v1,v2} u T1 u T2
        insert3(va.x, s1, s2, a0, a1, a2);
        r.x = med3(fmaxf(a0, mm), fmaxf(p, fminf(q, a1)), fminf(a2, nn));

        // out o+1: {v1,v2,v9} u T1 u T2
        insert3(vc.y, s1, s2, a0, a1, a2);
        r.y = med3(fmaxf(a0, mm), fmaxf(p, fminf(q, a1)), fminf(a2, nn));

        // out o+2: {v2,v9,v10} u T1 u T2
        insert3(va.z, t1, t2, a0, a1, a2);
        r.z = med3(fmaxf(a0, mm), fmaxf(p, fminf(q, a1)), fminf(a2, nn));

        // out o+3: {v9,v10,v11} u T1 u T2
        insert3(vc.w, t1, t2, a0, a1, a2);
        r.w = med3(fmaxf(a0, mm), fmaxf(p, fminf(q, a1)), fminf(a2, nn));

        *(float4*)(yo + o) = r;
    }
}

extern "C" void kernel_launch(void* const* d_in, const int* in_sizes, int n_in,
                              void* d_out, int out_size) {
    const float* x = (const float*)d_in[0];
    float* y = (float*)d_out;
    const int rows = in_sizes[0] / ROW_L;           // B*C = 2048
    median9_kernel<<<rows * SEGS_PER_ROW, NTHREADS>>>(x, y);
}